// round 16
// baseline (speedup 1.0000x reference)
#include <cuda_runtime.h>
#include <cuda_fp16.h>
#include <cstdint>

#define ADD_F32X2(out, a, b) \
    asm("add.rn.f32x2 %0, %1, %2;" : "=l"(out) : "l"(a), "l"(b))
#define PACK_B64(out, lo, hi) \
    asm("mov.b64 %0, {%1, %2};" : "=l"(out) : "r"(lo), "r"(hi))

constexpr int S = 512, H = 8, D = 64;
constexpr int TI = 32;     // i-tile
constexpr int TJ = 64;     // j-tile
constexpr int HSTR = 72;   // halves per smem row (144B, 16B-aligned, conflict-free)
constexpr int NTILES = (S / TI) * (S / TJ) * 2 * H;  // 16*8*16 = 2048
constexpr int NCTA = 296;  // 2 per SM x 148 SMs: exactly one wave, persistent

// -0.125 * 2^112 = -2^109 (exact fp32): undoes the 2^-112 bit-cast scaling.
#define OUT_SCALE_BITS 0xF6000000u

__global__ __launch_bounds__(256, 2)
void l1attn_kernel(const float* __restrict__ q, const float* __restrict__ k,
                   float* __restrict__ out) {
    __shared__ __align__(16) __half buf[2][(TI + TJ) * HSTR];

    const int tid = threadIdx.x;
    const int cta = blockIdx.x;

    union HU { __half2 h; unsigned u; };
    union U  { uint4 u4; __half2 h2[4]; };

    // Per-thread fill slots: q has TI*16=512 float4 slots (2/thread),
    // k has TJ*16=1024 slots (4/thread).
    float4 pq[2], pk[4];

    // ---- LDG next tile's fill data into registers (issue only) ----
    #define LOAD_TILE_REGS(T)                                                  \
        {                                                                      \
            const int bh_ = (T) >> 7;                                          \
            const int b_  = bh_ >> 3;                                          \
            const int h_  = bh_ & 7;                                           \
            const int i0_ = ((T) & 15) << 5;                                   \
            const int j0_ = (((T) >> 4) & 7) << 6;                             \
            _Pragma("unroll")                                                  \
            for (int u = 0; u < 2; ++u) {                                      \
                const int idx = tid + 256 * u;                                 \
                const int r = idx >> 4, dv = idx & 15;                         \
                pq[u] = *reinterpret_cast<const float4*>(                      \
                    q + (((b_ * S + i0_ + r) * H + h_) * D) + 4 * dv);         \
            }                                                                  \
            _Pragma("unroll")                                                  \
            for (int u = 0; u < 4; ++u) {                                      \
                const int idx = tid + 256 * u;                                 \
                const int r = idx >> 4, dv = idx & 15;                         \
                pk[u] = *reinterpret_cast<const float4*>(                      \
                    k + (((b_ * S + j0_ + r) * H + h_) * D) + 4 * dv);         \
            }                                                                  \
        }

    // ---- Convert + store staged registers into smem buffer BUFI ----
    #define STS_TILE(BUFI)                                                     \
        {                                                                      \
            __half* qs_ = buf[BUFI];                                           \
            __half* ks_ = buf[BUFI] + TI * HSTR;                               \
            _Pragma("unroll")                                                  \
            for (int u = 0; u < 2; ++u) {                                      \
                const int idx = tid + 256 * u;                                 \
                const int r = idx >> 4, dv = idx & 15;                         \
                HU h0, h1;                                                     \
                h0.h = __floats2half2_rn(pq[u].x, pq[u].y);                    \
                h1.h = __floats2half2_rn(pq[u].z, pq[u].w);                    \
                *reinterpret_cast<uint2*>(qs_ + r * HSTR + 4 * dv) =           \
                    make_uint2(h0.u, h1.u);                                    \
            }                                                                  \
            _Pragma("unroll")                                                  \
            for (int u = 0; u < 4; ++u) {                                      \
                const int idx = tid + 256 * u;                                 \
                const int r = idx >> 4, dv = idx & 15;                         \
                HU h0, h1;                                                     \
                h0.h = __floats2half2_rn(-pk[u].x, -pk[u].y);                  \
                h1.h = __floats2half2_rn(-pk[u].z, -pk[u].w);                  \
                *reinterpret_cast<uint2*>(ks_ + r * HSTR + 4 * dv) =           \
                    make_uint2(h0.u, h1.u);                                    \
            }                                                                  \
        }

    const int tx = tid & 15;            // i: i = tx + 16*c, c<2
    const int ty = tid >> 4;            // j: j = ty + 16*e, e<4
    const float sc = __uint_as_float(OUT_SCALE_BITS);   // -2^109

    // Prologue: stage + store tile 0.
    int t = cta;
    LOAD_TILE_REGS(t)
    STS_TILE(0)
    __syncthreads();

    int cur = 0;
    while (true) {
        const int tn = t + NCTA;
        const bool more = (tn < NTILES);
        if (more) LOAD_TILE_REGS(tn)    // LDGs overlap the compute below

        // ---- Compute tile t from buf[cur] ----
        const __half* qb = buf[cur] + tx * HSTR;
        const __half* kb = buf[cur] + TI * HSTR + ty * HSTR;

        unsigned long long acc[2][4];
        #pragma unroll
        for (int c = 0; c < 2; ++c)
            #pragma unroll
            for (int e = 0; e < 4; ++e) acc[c][e] = 0ull;

        #pragma unroll
        for (int gp = 0; gp < 2; ++gp) {
            U qv[2][2][2];   // [c][g2][half-of-32B]
            #pragma unroll
            for (int c = 0; c < 2; ++c)
                #pragma unroll
                for (int g2 = 0; g2 < 2; ++g2) {
                    const __half* qr = qb + 16 * c * HSTR + (2 * gp + g2) * 16;
                    qv[c][g2][0].u4 = *reinterpret_cast<const uint4*>(qr);
                    qv[c][g2][1].u4 = *reinterpret_cast<const uint4*>(qr + 8);
                }
            #pragma unroll
            for (int e = 0; e < 4; ++e) {
                U kv[2][2];
                #pragma unroll
                for (int g2 = 0; g2 < 2; ++g2) {
                    const __half* kr = kb + 16 * e * HSTR + (2 * gp + g2) * 16;
                    kv[g2][0].u4 = *reinterpret_cast<const uint4*>(kr);
                    kv[g2][1].u4 = *reinterpret_cast<const uint4*>(kr + 8);
                }
                #pragma unroll
                for (int c = 0; c < 2; ++c) {
                    __half2 a[2];
                    #pragma unroll
                    for (int g2 = 0; g2 < 2; ++g2) {
                        __half2 s[8];
                        #pragma unroll
                        for (int w = 0; w < 4; ++w)
                            s[w] = __hadd2(qv[c][g2][0].h2[w], kv[g2][0].h2[w]);
                        #pragma unroll
                        for (int w = 0; w < 4; ++w)
                            s[4 + w] = __hadd2(qv[c][g2][1].h2[w], kv[g2][1].h2[w]);
                        const __half2 t0 = __hadd2(__habs2(s[0]), __habs2(s[1]));
                        const __half2 t1 = __hadd2(__habs2(s[2]), __habs2(s[3]));
                        const __half2 t2 = __hadd2(__habs2(s[4]), __habs2(s[5]));
                        const __half2 t3 = __hadd2(__habs2(s[6]), __habs2(s[7]));
                        const __half2 u0 = __hadd2(t0, t1);
                        const __half2 u1 = __hadd2(t2, t3);
                        a[g2] = __hadd2(u0, u1);
                    }
                    HU m; m.h = __hadd2(a[0], a[1]);   // 32-term fp16 group sum
                    const unsigned lo = (m.u & 0x7FFFu) << 13;     // exact bit-cast
                    const unsigned hi = (m.u >> 3) & 0x3FFFE000u;  // (alu pipe)
                    unsigned long long p, tt;
                    PACK_B64(p, lo, hi);
                    ADD_F32X2(tt, acc[c][e], p);
                    acc[c][e] = tt;
                }
            }
        }

        // ---- Writeback tile t ----
        {
            const int bh = t >> 7;
            const int i0 = (t & 15) << 5;
            const int j0 = ((t >> 4) & 7) << 6;
            #pragma unroll
            for (int e = 0; e < 4; ++e) {
                const int j = j0 + ty + 16 * e;
                float* orow = out + ((size_t)bh * S + j) * S + i0;
                #pragma unroll
                for (int c = 0; c < 2; ++c) {
                    const unsigned long long a = acc[c][e];
                    const float lo = __uint_as_float((unsigned)(a & 0xFFFFFFFFu));
                    const float hi = __uint_as_float((unsigned)(a >> 32));
                    orow[tx + 16 * c] = sc * (lo + hi);
                }
            }
        }

        if (!more) break;
        STS_TILE(cur ^ 1)
        __syncthreads();     // one bar per tile (double buffer)
        cur ^= 1;
        t = tn;
    }
    #undef LOAD_TILE_REGS
    #undef STS_TILE
}

extern "C" void kernel_launch(void* const* d_in, const int* in_sizes, int n_in,
                              void* d_out, int out_size) {
    const float* q = (const float*)d_in[0];
    const float* k = (const float*)d_in[1];
    float* out     = (float*)d_out;
    l1attn_kernel<<<NCTA, 256>>>(q, k, out);
}